// round 7
// baseline (speedup 1.0000x reference)
#include <cuda_runtime.h>

#define B_ 64
#define R_ 32
#define N_ 16384
#define D_ 64
#define O_ 8
#define SPLIT_ 8
#define CHUNK_ (N_ / SPLIT_)    /* 2048 = 256 threads * 8 n */
#define THREADS_ 256

// Plain-store partials: every slot written every launch -> no zeroing pass.
__device__ __align__(16) float g_part[B_][SPLIT_][D_];
__device__ float g_cnt[B_][SPLIT_];
// Completion counters (zero-init .bss; finalizer resets them each launch).
__device__ unsigned g_done[B_];

// ---------------------------------------------------------------------------
// Single launch. grid = (B, SPLIT), block = 256; thread owns 8 consecutive n
// (warp = 256 contiguous mask bytes per array -> fully coalesced uint2 loads).
// o_types is loaded ONLY where a mask hit exists (cuts ~2.4 MB of traffic).
// Gather is two-pass (norm pass + L1-hit rescale pass) to cap register
// pressure at <=51 regs -> 5 blocks/SM occupancy.
// The last block to finish each b finalizes that b's 32 outputs.
// ---------------------------------------------------------------------------
__global__ __launch_bounds__(THREADS_, 5)
void ssfw_fused(const float* __restrict__ l_local,
                const float* __restrict__ hctx,
                const float* __restrict__ lambda_so,
                const int*   __restrict__ center_o,
                const int*   __restrict__ o_types,
                const void*  __restrict__ adj,
                const void*  __restrict__ two,
                float*       __restrict__ out) {
    const int b    = blockIdx.x;
    const int part = blockIdx.y;
    const int tid  = threadIdx.x;

    __shared__ __align__(16) float s_acc[D_];
    __shared__ int  sh_bytes;       // 1 if masks are packed bytes (numpy bool)
    __shared__ int  s_cnt;
    __shared__ int  s_last;
    if (tid == 0) { sh_bytes = 0; s_cnt = 0; }
    if (tid < D_) s_acc[tid] = 0.0f;

    // ---- round-1 loads issued up front (independent; high MLP) ----
    // probe: first 2KB of each mask array (identical across blocks, L2-hot)
    unsigned pa0 = ((const unsigned*)adj)[tid];
    unsigned pt0 = ((const unsigned*)two)[tid];
    unsigned pa1 = ((const unsigned*)adj)[tid + 256];
    unsigned pt1 = ((const unsigned*)two)[tid + 256];

    const int       n_base = part * CHUNK_ + tid * 8;
    const long long mi     = (long long)b * N_ + n_base;

    // speculative byte-view mask loads: 8 bytes per array (8B-aligned)
    uint2 a2 = *(const uint2*)((const unsigned char*)adj + mi);
    uint2 t2 = *(const uint2*)((const unsigned char*)two + mi);
    const int ctr = center_o[b];

    // classify: any probe word outside {0, 1, 0x3F800000} => packed bytes
    {
        int isb = 0;
        #pragma unroll
        for (int j = 0; j < 4; j++) {
            unsigned v = (j == 0) ? pa0 : (j == 1) ? pt0 : (j == 2) ? pa1 : pt1;
            if (v != 0u && v != 1u && v != 0x3F800000u) isb = 1;
        }
        if (isb) atomicOr(&sh_bytes, 1);
    }
    __syncthreads();

    // per-4-group hit bytes: u[0] covers n = mi..mi+3, u[1] covers mi+4..mi+7
    unsigned u[2];
    if (sh_bytes) {
        u[0] = a2.x | t2.x;
        u[1] = a2.y | t2.y;
    } else {
        // word masks: nonzero == true for BOTH int32 0/1 and f32 0.0/1.0
        const uint4* wa = (const uint4*)((const int*)adj + mi);
        const uint4* wt = (const uint4*)((const int*)two + mi);
        uint4 a0 = wa[0], a1 = wa[1], b0 = wt[0], b1 = wt[1];
        u[0] = ((a0.x | b0.x) ? 1u : 0u)       | ((a0.y | b0.y) ? 0x100u : 0u)
             | ((a0.z | b0.z) ? 0x10000u : 0u) | ((a0.w | b0.w) ? 0x1000000u : 0u);
        u[1] = ((a1.x | b1.x) ? 1u : 0u)       | ((a1.y | b1.y) ? 0x100u : 0u)
             | ((a1.z | b1.z) ? 0x10000u : 0u) | ((a1.w | b1.w) ? 0x1000000u : 0u);
    }

    int localc = 0;
    #pragma unroll
    for (int g = 0; g < 2; g++) {
        if (!u[g]) continue;                       // ~78% of 4-groups skip
        const long long mg = mi + g * 4;
        const int4 ov = *(const int4*)(o_types + mg);   // conditional load
        const int  oo[4] = { ov.x, ov.y, ov.z, ov.w };
        #pragma unroll
        for (int j = 0; j < 4; j++) {
            if (((u[g] >> (8 * j)) & 0xffu) && oo[j] == ctr) {
                localc++;
                const float4* row = (const float4*)(hctx + (mg + j) * D_);
                // pass A: squared norm (row not kept live -> low reg pressure)
                float sq = 0.0f;
                #pragma unroll
                for (int i = 0; i < 16; i++) {
                    float4 v = row[i];
                    sq += v.x * v.x + v.y * v.y + v.z * v.z + v.w * v.w;
                }
                float rn = rsqrtf(fmaxf(sq, 1e-12f));
                // pass B: re-read (L1 hit) + scaled accumulate
                #pragma unroll
                for (int i = 0; i < 16; i++) {
                    float4 v = row[i];
                    atomicAdd(&s_acc[4 * i + 0], v.x * rn);
                    atomicAdd(&s_acc[4 * i + 1], v.y * rn);
                    atomicAdd(&s_acc[4 * i + 2], v.z * rn);
                    atomicAdd(&s_acc[4 * i + 3], v.w * rn);
                }
            }
        }
    }
    if (localc) atomicAdd(&s_cnt, localc);
    __syncthreads();

    // ---- publish partials ----
    if (tid < D_) g_part[b][part][tid] = s_acc[tid];
    if (tid == 0) g_cnt[b][part] = (float)s_cnt;

    // ---- last-block-done detection ----
    if (tid == 0) {
        __threadfence();
        unsigned old = atomicAdd(&g_done[b], 1u);
        s_last = (old == SPLIT_ - 1);
    }
    __syncthreads();
    if (!s_last) return;

    // ---- finalize b (this block only) ----
    __shared__ __align__(16) float s_sum[D_];
    __shared__ float s_nv;
    if (tid < D_) {
        float acc = 0.0f;
        #pragma unroll
        for (int p = 0; p < SPLIT_; p++) acc += g_part[b][p][tid];
        s_sum[tid] = acc;
    }
    if (tid == 0) {
        float nv = 0.0f;
        #pragma unroll
        for (int p = 0; p < SPLIT_; p++) nv += g_cnt[b][p];
        s_nv = nv;
        g_done[b] = 0;                  // reset for next graph replay
    }
    __syncthreads();

    const int warp = tid >> 5;          // 8 warps
    const int lane = tid & 31;
    const float  nv = s_nv;
    const float2 sv = *(const float2*)(&s_sum[lane * 2]);

    #pragma unroll
    for (int rr = 0; rr < 4; rr++) {    // warp w handles r = w, w+8, w+16, w+24
        const int r = warp + rr * 8;
        const float2* lrow = (const float2*)(l_local + ((long long)b * R_ + r) * D_);
        float2 lv = lrow[lane];

        float sq = lv.x * lv.x + lv.y * lv.y;
        float dp = lv.x * sv.x + lv.y * sv.y;
        #pragma unroll
        for (int o = 16; o > 0; o >>= 1) {
            sq += __shfl_xor_sync(0xffffffffu, sq, o);
            dp += __shfl_xor_sync(0xffffffffu, dp, o);
        }
        if (lane == 0) {
            float rinv = rsqrtf(fmaxf(sq, 1e-12f));
            float avg  = rinv * dp / fmaxf(nv, 1e-9f);
            float lam  = lambda_so[r * O_ + ctr];
            float w    = fmaxf(lam / fmaxf(nv, 1.0f), 0.0f) * (1.0f - avg);
            out[b * R_ + r] = w;
        }
    }
}

// ---------------------------------------------------------------------------
// Launch contract
// Inputs (metadata order): 0 l_local [B,R,D] f32, 1 h_context [B,N,D] f32,
// 2 lambda_so [R,O] f32, 3 center_o [B] i32, 4 o_types [B,N] i32,
// 5 adj_mask [B,N] bool, 6 two_hop_mask [B,N] bool.  Output [B,R] f32.
// ---------------------------------------------------------------------------
extern "C" void kernel_launch(void* const* d_in, const int* in_sizes, int n_in,
                              void* d_out, int out_size) {
    const float* l_local   = (const float*)d_in[0];
    const float* h_context = (const float*)d_in[1];
    const float* lambda_so = (const float*)d_in[2];
    const int*   center_o  = (const int*)d_in[3];
    const int*   o_types   = (const int*)d_in[4];
    const void*  adj_mask  = d_in[5];
    const void*  two_mask  = d_in[6];
    float*       out       = (float*)d_out;

    ssfw_fused<<<dim3(B_, SPLIT_), THREADS_>>>(l_local, h_context, lambda_so,
                                               center_o, o_types,
                                               adj_mask, two_mask, out);
}

// round 8
// speedup vs baseline: 3.8523x; 3.8523x over previous
#include <cuda_runtime.h>

#define B_ 64
#define R_ 32
#define N_ 16384
#define D_ 64
#define O_ 8
#define SPLIT_ 16
#define CHUNK_ (N_ / SPLIT_)    /* 1024 = 256 threads * 4 n */
#define THREADS_ 256
#define NWARP_ (THREADS_ / 32)

// Plain-store partials: every slot written every launch -> no zeroing pass.
__device__ __align__(16) float g_part[B_][SPLIT_][D_];
__device__ float g_cnt[B_][SPLIT_];
// Completion counters (zero-init .bss; finalizer resets them each launch).
__device__ unsigned g_done[B_];

// ---------------------------------------------------------------------------
// Single launch. grid = (B, SPLIT), block = 256; thread owns 4 consecutive n
// (warp = 512 contiguous mask bytes -> fully coalesced).
// Sparse hctx rows are gathered WARP-COOPERATIVELY: one coalesced 256B load
// per hit, norm via butterfly reduce, accumulate into per-lane registers.
// No shared atomics. Last block per b finalizes its 32 outputs.
// ---------------------------------------------------------------------------
__global__ __launch_bounds__(THREADS_)
void ssfw_fused(const float* __restrict__ l_local,
                const float* __restrict__ hctx,
                const float* __restrict__ lambda_so,
                const int*   __restrict__ center_o,
                const int*   __restrict__ o_types,
                const void*  __restrict__ adj,
                const void*  __restrict__ two,
                float*       __restrict__ out) {
    const int b    = blockIdx.x;
    const int part = blockIdx.y;
    const int tid  = threadIdx.x;
    const int warp = tid >> 5;
    const int lane = tid & 31;

    __shared__ __align__(16) float s_part[NWARP_][D_];
    __shared__ int  sh_bytes;       // 1 if masks are packed bytes (numpy bool)
    __shared__ int  s_cnt;
    __shared__ int  s_last;
    if (tid == 0) { sh_bytes = 0; s_cnt = 0; }

    // ---- round-1 loads issued up front (independent; high MLP) ----
    // probe: first 2KB of each mask array (identical across blocks, L2-hot)
    unsigned pa0 = ((const unsigned*)adj)[tid];
    unsigned pt0 = ((const unsigned*)two)[tid];
    unsigned pa1 = ((const unsigned*)adj)[tid + 256];
    unsigned pt1 = ((const unsigned*)two)[tid + 256];

    const int n_glob = b * N_ + part * CHUNK_ + tid * 4;   // fits in int (max 1M)

    // speculative byte-view mask loads (valid for any dtype >= 1 byte/elem)
    unsigned bva = *(const unsigned*)((const unsigned char*)adj + n_glob);
    unsigned bvt = *(const unsigned*)((const unsigned char*)two + n_glob);
    // o_types: speculative, issued concurrently with masks (R6 lesson)
    const int4 ov  = *(const int4*)(o_types + n_glob);
    const int  ctr = center_o[b];

    // classify: any probe word outside {0, 1, 0x3F800000} => packed bytes
    {
        int isb = 0;
        #pragma unroll
        for (int j = 0; j < 4; j++) {
            unsigned v = (j == 0) ? pa0 : (j == 1) ? pt0 : (j == 2) ? pa1 : pt1;
            if (v != 0u && v != 1u && v != 0x3F800000u) isb = 1;
        }
        if (isb) atomicOr(&sh_bytes, 1);
    }
    __syncthreads();

    unsigned m[4];
    if (sh_bytes) {
        unsigned u = bva | bvt;
        m[0] = u & 0xffu;         m[1] = (u >> 8) & 0xffu;
        m[2] = (u >> 16) & 0xffu; m[3] = u >> 24;
    } else {
        // word masks: nonzero == true for BOTH int32 0/1 and f32 0.0/1.0
        uint4 va = *(const uint4*)((const int*)adj + n_glob);
        uint4 vt = *(const uint4*)((const int*)two + n_glob);
        m[0] = va.x | vt.x; m[1] = va.y | vt.y;
        m[2] = va.z | vt.z; m[3] = va.w | vt.w;
    }

    // 4-bit valid pattern for this thread's 4 n
    int hb = 0;
    if (m[0] && ov.x == ctr) hb |= 1;
    if (m[1] && ov.y == ctr) hb |= 2;
    if (m[2] && ov.z == ctr) hb |= 4;
    if (m[3] && ov.w == ctr) hb |= 8;

    // ---- warp-cooperative gather: per-lane register accumulator ----
    // lane owns dims {2*lane, 2*lane+1}
    float accx = 0.0f, accy = 0.0f;
    int   wcnt = 0;
    unsigned hitmask = __ballot_sync(0xffffffffu, hb != 0);
    while (hitmask) {
        int src = __ffs(hitmask) - 1;
        hitmask &= hitmask - 1;
        int shb = __shfl_sync(0xffffffffu, hb, src);
        int snb = __shfl_sync(0xffffffffu, n_glob, src);
        #pragma unroll
        for (int j = 0; j < 4; j++) {
            if ((shb >> j) & 1) {
                wcnt++;
                const float2 v = ((const float2*)(hctx + (long long)(snb + j) * D_))[lane];
                float sq = v.x * v.x + v.y * v.y;
                #pragma unroll
                for (int o = 16; o > 0; o >>= 1)
                    sq += __shfl_xor_sync(0xffffffffu, sq, o);
                float rn = rsqrtf(fmaxf(sq, 1e-12f));
                accx += v.x * rn;
                accy += v.y * rn;
            }
        }
    }
    s_part[warp][lane * 2]     = accx;
    s_part[warp][lane * 2 + 1] = accy;
    if (lane == 0 && wcnt) atomicAdd(&s_cnt, wcnt);
    __syncthreads();

    // ---- reduce 8 warp slices, publish partials ----
    if (tid < D_) {
        float acc = 0.0f;
        #pragma unroll
        for (int w = 0; w < NWARP_; w++) acc += s_part[w][tid];
        g_part[b][part][tid] = acc;
    }
    if (tid == 0) g_cnt[b][part] = (float)s_cnt;

    // ---- last-block-done detection ----
    if (tid == 0) {
        __threadfence();
        unsigned old = atomicAdd(&g_done[b], 1u);
        s_last = (old == SPLIT_ - 1);
    }
    __syncthreads();
    if (!s_last) return;

    // ---- finalize b (this block only) ----
    __shared__ __align__(16) float s_sum[D_];
    __shared__ float s_nv;
    if (tid < D_) {
        float acc = 0.0f;
        #pragma unroll
        for (int p = 0; p < SPLIT_; p++) acc += g_part[b][p][tid];
        s_sum[tid] = acc;
    }
    if (tid == 0) {
        float nv = 0.0f;
        #pragma unroll
        for (int p = 0; p < SPLIT_; p++) nv += g_cnt[b][p];
        s_nv = nv;
        g_done[b] = 0;                  // reset for next graph replay
    }
    __syncthreads();

    const float  nv = s_nv;
    const float2 sv = *(const float2*)(&s_sum[lane * 2]);

    #pragma unroll
    for (int rr = 0; rr < 4; rr++) {    // warp w handles r = w, w+8, w+16, w+24
        const int r = warp + rr * 8;
        const float2* lrow = (const float2*)(l_local + ((long long)b * R_ + r) * D_);
        float2 lv = lrow[lane];

        float sq = lv.x * lv.x + lv.y * lv.y;
        float dp = lv.x * sv.x + lv.y * sv.y;
        #pragma unroll
        for (int o = 16; o > 0; o >>= 1) {
            sq += __shfl_xor_sync(0xffffffffu, sq, o);
            dp += __shfl_xor_sync(0xffffffffu, dp, o);
        }
        if (lane == 0) {
            float rinv = rsqrtf(fmaxf(sq, 1e-12f));
            float avg  = rinv * dp / fmaxf(nv, 1e-9f);
            float lam  = lambda_so[r * O_ + ctr];
            float w    = fmaxf(lam / fmaxf(nv, 1.0f), 0.0f) * (1.0f - avg);
            out[b * R_ + r] = w;
        }
    }
}

// ---------------------------------------------------------------------------
// Launch contract
// Inputs (metadata order): 0 l_local [B,R,D] f32, 1 h_context [B,N,D] f32,
// 2 lambda_so [R,O] f32, 3 center_o [B] i32, 4 o_types [B,N] i32,
// 5 adj_mask [B,N] bool, 6 two_hop_mask [B,N] bool.  Output [B,R] f32.
// ---------------------------------------------------------------------------
extern "C" void kernel_launch(void* const* d_in, const int* in_sizes, int n_in,
                              void* d_out, int out_size) {
    const float* l_local   = (const float*)d_in[0];
    const float* h_context = (const float*)d_in[1];
    const float* lambda_so = (const float*)d_in[2];
    const int*   center_o  = (const int*)d_in[3];
    const int*   o_types   = (const int*)d_in[4];
    const void*  adj_mask  = d_in[5];
    const void*  two_mask  = d_in[6];
    float*       out       = (float*)d_out;

    ssfw_fused<<<dim3(B_, SPLIT_), THREADS_>>>(l_local, h_context, lambda_so,
                                               center_o, o_types,
                                               adj_mask, two_mask, out);
}